// round 10
// baseline (speedup 1.0000x reference)
#include <cuda_runtime.h>
#include <cuda_fp16.h>
#include <cstdint>

// MoeGate: logits via mma.sync m16n8k16 fp16 (3-term fp16 split) + exact-fp32
// fixup. R10: gate restructured as 2 CTAs/SM (BM=64, 256 thr) so co-resident
// CTAs hide each other's sync/staging latency (R9 profile: all pipes <44%,
// wall 2570cyc/chunk vs ~1000cyc work -- latency-bound with 1 CTA/SM).
// Fixup spread over 592 CTAs (FTOK=8) to cut the serial W-sweep wall.

#define HDIM   2048
#define NEXP   64
#define KTOP   8
#define BM     64
#define KC     32
#define NCHUNK (HDIM / KC)
#define NTHR   256
#define PH     40                          // smem pitch in halves (conflict-free)
#define AH_OFF 0
#define AL_OFF (BM * PH)                   // 2560 halves
#define BH_OFF (2 * BM * PH)               // 5120
#define BL_OFF (BH_OFF + NEXP * PH)        // 7680
#define STG_HALVES (BL_OFF + NEXP * PH)    // 10240 halves = 20480 B/stage
#define LG_PITCH 65
#define NBLK   256                         // T / BM
#define FTOK   8
#define FGRID  592

__device__ float g_pi_part[NBLK * NEXP];
__device__ float g_cnt_part[NBLK * NEXP];
__device__ int   g_flag_cnt = 0;
__device__ int   g_flag_idx[16384];

__device__ __forceinline__ void mma_f16(float* c, const uint32_t* a, const uint32_t* b) {
    asm volatile(
        "mma.sync.aligned.m16n8k16.row.col.f32.f16.f16.f32 "
        "{%0,%1,%2,%3}, {%4,%5,%6,%7}, {%8,%9}, {%0,%1,%2,%3};"
        : "+f"(c[0]), "+f"(c[1]), "+f"(c[2]), "+f"(c[3])
        : "r"(a[0]), "r"(a[1]), "r"(a[2]), "r"(a[3]), "r"(b[0]), "r"(b[1]));
}

__device__ __forceinline__ void split_h2(float a, float b, uint32_t& hi, uint32_t& lo) {
    __half ha = __float2half_rn(a), hb = __float2half_rn(b);
    float ra = a - __half2float(ha), rb = b - __half2float(hb);
    __half2 h = __halves2half2(ha, hb);
    __half2 l = __halves2half2(__float2half_rn(ra), __float2half_rn(rb));
    hi = *(uint32_t*)&h;
    lo = *(uint32_t*)&l;
}

__global__ __launch_bounds__(NTHR, 2) void gate_kernel(
    const float* __restrict__ x, const float* __restrict__ w,
    float* __restrict__ out, int T, int S)
{
    extern __shared__ char smraw[];
    __half* smemh = (__half*)smraw;
    float*  lg    = (float*)smraw;        // logits overlay after GEMM
    __shared__ float cnt_s[NEXP];

    const int tid  = threadIdx.x;
    const int wid  = tid >> 5;
    const int lane = tid & 31;
    const int grp  = lane >> 2;
    const int qid  = lane & 3;
    const int t0   = blockIdx.x * BM;
    const int mrow0 = (wid & 3) * 16;     // 4 warps in M
    const int ncol0 = (wid >> 2) * 32;    // 2 warps in N

    if (tid < NEXP) cnt_s[tid] = 0.f;

    float acc[4][4];
#pragma unroll
    for (int j = 0; j < 4; j++)
#pragma unroll
        for (int k = 0; k < 4; k++) acc[j][k] = 0.f;

    const float* xbase = x + (size_t)t0 * HDIM;

    float4 rx[2], rw[2];
    auto ldg_chunk = [&](int c) {
#pragma unroll
        for (int i = 0; i < 2; i++) {     // A: 64 rows x 8 segs = 512
            int id = tid + NTHR * i;
            rx[i] = *(const float4*)(xbase + (size_t)(id >> 3) * HDIM + c * KC + (id & 7) * 4);
        }
#pragma unroll
        for (int i = 0; i < 2; i++) {     // B: 64 rows x 8 segs = 512
            int id = tid + NTHR * i;
            rw[i] = *(const float4*)(w + (size_t)(id >> 3) * HDIM + c * KC + (id & 7) * 4);
        }
    };
    auto sts_chunk = [&](int st) {
        __half* stg = smemh + st * STG_HALVES;
#pragma unroll
        for (int i = 0; i < 2; i++) {
            int id = tid + NTHR * i;
            int idx = (id >> 3) * PH + (id & 7) * 4;
            uint32_t h0, l0, h1, l1;
            split_h2(rx[i].x, rx[i].y, h0, l0);
            split_h2(rx[i].z, rx[i].w, h1, l1);
            *(uint2*)(stg + AH_OFF + idx) = make_uint2(h0, h1);
            *(uint2*)(stg + AL_OFF + idx) = make_uint2(l0, l1);
        }
#pragma unroll
        for (int i = 0; i < 2; i++) {
            int id = tid + NTHR * i;
            int idx = (id >> 3) * PH + (id & 7) * 4;
            uint32_t h0, l0, h1, l1;
            split_h2(rw[i].x, rw[i].y, h0, l0);
            split_h2(rw[i].z, rw[i].w, h1, l1);
            *(uint2*)(stg + BH_OFF + idx) = make_uint2(h0, h1);
            *(uint2*)(stg + BL_OFF + idx) = make_uint2(l0, l1);
        }
    };

    ldg_chunk(0);

    for (int c = 0; c < NCHUNK; c++) {
        const int st = c & 1;
        sts_chunk(st);
        __syncthreads();
        if (c + 1 < NCHUNK) ldg_chunk(c + 1);

        const __half* stg = smemh + st * STG_HALVES;
        const uint32_t* Ah = (const uint32_t*)(stg + AH_OFF);
        const uint32_t* Al = (const uint32_t*)(stg + AL_OFF);
        const uint32_t* Bh = (const uint32_t*)(stg + BH_OFF);
        const uint32_t* Bl = (const uint32_t*)(stg + BL_OFF);

        // q in {0,1}: k-slice of 16. uint32 (half2) units, pitch PH/2 = 20.
#pragma unroll
        for (int q = 0; q < 2; q++) {
            const int kb = 8 * q + qid;
            uint32_t ah[4], al[4];
            {
                int r0 = (mrow0 + grp) * 20, r1 = (mrow0 + grp + 8) * 20;
                ah[0] = Ah[r0 + kb];     ah[1] = Ah[r1 + kb];
                ah[2] = Ah[r0 + kb + 4]; ah[3] = Ah[r1 + kb + 4];
                al[0] = Al[r0 + kb];     al[1] = Al[r1 + kb];
                al[2] = Al[r0 + kb + 4]; al[3] = Al[r1 + kb + 4];
            }
            uint32_t bh[4][2], bl[4][2];
#pragma unroll
            for (int nt = 0; nt < 4; nt++) {
                int nr = (ncol0 + nt * 8 + grp) * 20;
                bh[nt][0] = Bh[nr + kb]; bh[nt][1] = Bh[nr + kb + 4];
                bl[nt][0] = Bl[nr + kb]; bl[nt][1] = Bl[nr + kb + 4];
            }
#pragma unroll
            for (int nt = 0; nt < 4; nt++) mma_f16(acc[nt], ah, bh[nt]);
#pragma unroll
            for (int nt = 0; nt < 4; nt++) mma_f16(acc[nt], ah, bl[nt]);
#pragma unroll
            for (int nt = 0; nt < 4; nt++) mma_f16(acc[nt], al, bh[nt]);
        }
        __syncthreads();
    }

    // ---- logits -> smem ----
#pragma unroll
    for (int nt = 0; nt < 4; nt++) {
        int row = mrow0 + grp;
        int col = ncol0 + nt * 8 + 2 * qid;
        lg[row * LG_PITCH + col]           = acc[nt][0];
        lg[row * LG_PITCH + col + 1]       = acc[nt][1];
        lg[(row + 8) * LG_PITCH + col]     = acc[nt][2];
        lg[(row + 8) * LG_PITCH + col + 1] = acc[nt][3];
    }
    __syncthreads();

    // ---- per-token epilogue (threads 0..63) ----
    if (tid < BM) {
        float sc[NEXP];
        float mx = -1e30f;
#pragma unroll
        for (int e = 0; e < NEXP; e++) { sc[e] = lg[tid * LG_PITCH + e]; mx = fmaxf(mx, sc[e]); }
        float sum = 0.f;
#pragma unroll
        for (int e = 0; e < NEXP; e++) { sc[e] = __expf(sc[e] - mx); sum += sc[e]; }
        float inv = 1.f / sum;
#pragma unroll
        for (int e = 0; e < NEXP; e++) sc[e] *= inv;
#pragma unroll
        for (int e = 0; e < NEXP; e++) lg[tid * LG_PITCH + e] = sc[e];

        float vsel[KTOP + 1]; int isel[KTOP + 1]; float wsum = 0.f;
#pragma unroll
        for (int j = 0; j < KTOP + 1; j++) {
            float bv = -1.f; int bi = 0;
#pragma unroll
            for (int e = 0; e < NEXP; e++) if (sc[e] > bv) { bv = sc[e]; bi = e; }
            vsel[j] = bv; isel[j] = bi;
#pragma unroll
            for (int e = 0; e < NEXP; e++) if (e == bi) sc[e] = -1.f;
            if (j < KTOP) { wsum += bv; atomicAdd(&cnt_s[bi], 1.f); }
        }
        bool flag = false;
#pragma unroll
        for (int j = 0; j < KTOP; j++)
            if (vsel[j] - vsel[j + 1] < vsel[j] * 1e-3f + 2e-6f) flag = true;

        size_t t = (size_t)t0 + tid;
        if (flag) {
            int p = atomicAdd(&g_flag_cnt, 1);
            g_flag_idx[p] = (int)t;
        }
        float rn = 1.f / (wsum + 1e-20f);
#pragma unroll
        for (int j = 0; j < KTOP; j++) {
            out[t * KTOP + j] = (float)isel[j];
            out[(size_t)T * KTOP + t * KTOP + j] = vsel[j] * rn;
        }
    }
    __syncthreads();

    if (tid < NEXP) {
        float pe = 0.f;
#pragma unroll 8
        for (int m = 0; m < BM; m++) pe += lg[m * LG_PITCH + tid];
        g_pi_part[blockIdx.x * NEXP + tid]  = pe;
        g_cnt_part[blockIdx.x * NEXP + tid] = cnt_s[tid];
    }
}

// Exact-fp32 fixup: sequential-k fma chain per (token, expert) -- identical
// arithmetic order to round-1's kernel (0 flips vs reference). 8 tokens/CTA
// across 592 CTAs so the serial 64-chunk W sweep is spread, not stacked.
__global__ __launch_bounds__(256) void fixup_kernel(
    const float* __restrict__ x, const float* __restrict__ w,
    float* __restrict__ out, int T)
{
    __shared__ float4 ws4[8 * 66];        // [kq][e]
    __shared__ float4 xs4[FTOK * 9];      // [t][kq]
    __shared__ float  lgs[FTOK][72];

    const int tid = threadIdx.x;
    const int e   = tid & 63;
    const int tp  = tid >> 6;             // 0..3 -> tokens 2tp, 2tp+1
    const int nflag = g_flag_cnt;

    const int wr0 = tid >> 3,        wq = tid & 7;
    const int wr1 = (tid + 256) >> 3;
    const int xt  = tid >> 3,        xq = tid & 7;   // tid<64: 8 tok x 8 segs

    for (int base = blockIdx.x * FTOK; base < nflag; base += FGRID * FTOK) {
        float acc0 = 0.f, acc1 = 0.f;

        int fi = 0;
        if (tid < 64)
            fi = (base + xt < nflag) ? g_flag_idx[base + xt] : g_flag_idx[base];

        float4 pw0 = *(const float4*)(w + (size_t)wr0 * HDIM + wq * 4);
        float4 pw1 = *(const float4*)(w + (size_t)wr1 * HDIM + wq * 4);
        float4 px  = (tid < 64) ? *(const float4*)(x + (size_t)fi * HDIM + xq * 4)
                                : make_float4(0.f, 0.f, 0.f, 0.f);

        for (int c = 0; c < 64; c++) {
            ws4[wq * 66 + wr0] = pw0;
            ws4[wq * 66 + wr1] = pw1;
            if (tid < 64) xs4[xt * 9 + xq] = px;
            __syncthreads();

            if (c < 63) {
                pw0 = *(const float4*)(w + (size_t)wr0 * HDIM + (c + 1) * 32 + wq * 4);
                pw1 = *(const float4*)(w + (size_t)wr1 * HDIM + (c + 1) * 32 + wq * 4);
                if (tid < 64)
                    px = *(const float4*)(x + (size_t)fi * HDIM + (c + 1) * 32 + xq * 4);
            }
#pragma unroll
            for (int kq = 0; kq < 8; kq++) {
                float4 wv = ws4[kq * 66 + e];
                float4 x0 = xs4[(2 * tp) * 9 + kq];
                float4 x1 = xs4[(2 * tp + 1) * 9 + kq];
                acc0 = fmaf(x0.x, wv.x, acc0); acc0 = fmaf(x0.y, wv.y, acc0);
                acc0 = fmaf(x0.z, wv.z, acc0); acc0 = fmaf(x0.w, wv.w, acc0);
                acc1 = fmaf(x1.x, wv.x, acc1); acc1 = fmaf(x1.y, wv.y, acc1);
                acc1 = fmaf(x1.z, wv.z, acc1); acc1 = fmaf(x1.w, wv.w, acc1);
            }
            __syncthreads();
        }

        lgs[2 * tp][e]     = acc0;
        lgs[2 * tp + 1][e] = acc1;
        __syncthreads();

        if (tid < FTOK && base + tid < nflag) {
            int t = g_flag_idx[base + tid];
            float sc[NEXP];
            float mx = -1e30f;
#pragma unroll
            for (int j = 0; j < NEXP; j++) { sc[j] = lgs[tid][j]; mx = fmaxf(mx, sc[j]); }
            float sum = 0.f;
#pragma unroll
            for (int j = 0; j < NEXP; j++) { sc[j] = __expf(sc[j] - mx); sum += sc[j]; }
            float inv = 1.f / sum;
#pragma unroll
            for (int j = 0; j < NEXP; j++) sc[j] *= inv;

            float wsel[KTOP]; int isel[KTOP]; float wsum = 0.f;
#pragma unroll
            for (int j = 0; j < KTOP; j++) {
                float bv = -1.f; int bi = 0;
#pragma unroll
                for (int e2 = 0; e2 < NEXP; e2++) if (sc[e2] > bv) { bv = sc[e2]; bi = e2; }
                wsel[j] = bv; isel[j] = bi; wsum += bv;
                sc[bi] = -1.f;
            }
            float rn = 1.f / (wsum + 1e-20f);
#pragma unroll
            for (int j = 0; j < KTOP; j++) {
                out[(size_t)t * KTOP + j] = (float)isel[j];
                out[(size_t)T * KTOP + (size_t)t * KTOP + j] = wsel[j] * rn;
            }
        }
        __syncthreads();
    }
}

__global__ void loss_kernel(float* __restrict__ out, int T, int S, int B) {
    __shared__ float red[256];
    int tid = threadIdx.x;
    if (tid == 0) g_flag_cnt = 0;            // reset for next graph replay
    int b = tid >> 6, e = tid & 63;
    float ps = 0.f, cs = 0.f;
    int blk0 = b * (NBLK / 4);
    for (int blk = blk0; blk < blk0 + NBLK / 4; blk++) {
        ps += g_pi_part[blk * NEXP + e];
        cs += g_cnt_part[blk * NEXP + e];
    }
    float pi = ps / (float)S;
    float fi = cs * ((float)NEXP / (float)(S * KTOP));
    red[tid] = pi * fi;
    __syncthreads();
    for (int s = 128; s > 0; s >>= 1) {
        if (tid < s) red[tid] += red[tid + s];
        __syncthreads();
    }
    if (tid == 0)
        out[(size_t)2 * T * KTOP] = red[0] * 0.01f / (float)B;
}

extern "C" void kernel_launch(void* const* d_in, const int* in_sizes, int n_in,
                              void* d_out, int out_size)
{
    const float* x = (const float*)d_in[0];
    const float* w = (const float*)d_in[1];
    float* out = (float*)d_out;

    int Hrt = in_sizes[1] / NEXP;    // 2048
    int T   = in_sizes[0] / Hrt;     // 16384
    int B   = 4;
    int S   = T / B;                 // 4096

    size_t smem_bytes = 2 * STG_HALVES * sizeof(__half);   // 40960
    cudaFuncSetAttribute(gate_kernel, cudaFuncAttributeMaxDynamicSharedMemorySize,
                         (int)smem_bytes);

    gate_kernel<<<T / BM, NTHR, smem_bytes>>>(x, w, out, T, S);
    fixup_kernel<<<FGRID, 256>>>(x, w, out, T);
    loss_kernel<<<1, 256>>>(out, T, S, B);
}

// round 11
// speedup vs baseline: 1.0540x; 1.0540x over previous
#include <cuda_runtime.h>
#include <cuda_fp16.h>
#include <cstdint>

// MoeGate: mma.sync m16n8k16 fp16 (3-term split) + exact-fp32 fixup.
// R11: warp tile 32x32 (halves operand dup) and B served straight from
// precomputed fragment-layout hi/lo planes in global (L2-resident, no B smem).
// R10 evidence: gate pinned at 87us by L1 wavefront traffic (48%), not CTAs.

#define HDIM   2048
#define NEXP   64
#define KTOP   8
#define BM     64
#define KC     32
#define NCHUNK (HDIM / KC)
#define NTHR   128                         // 4 warps: 2M x 2N, 32x32 tile each
#define PH     40                          // A smem pitch in halves
#define STG_HALVES (2 * BM * PH)           // hi+lo planes: 5120 halves = 10KB
#define LG_PITCH 65
#define NBLK   256                         // T / BM
#define FTOK   32
#define FGRID  148

__device__ float g_pi_part[NBLK * NEXP];
__device__ float g_cnt_part[NBLK * NEXP];
__device__ int   g_flag_cnt = 0;
__device__ int   g_flag_idx[16384];
// W fragment planes: uint4 index = (c*8 + g*4 + r4)*32 + lane
// reg r = r4*4+i encodes q=r>>3, nt=(r>>1)&3, b=r&1;
// n = g*32 + nt*8 + (lane>>2); k = c*32 + 16q + 2*(lane&3) + 8b, pair (k,k+1)
__device__ uint4 g_whi[16384];
__device__ uint4 g_wlo[16384];

__device__ __forceinline__ void mma_f16(float* c, const uint32_t* a, const uint32_t* b) {
    asm volatile(
        "mma.sync.aligned.m16n8k16.row.col.f32.f16.f16.f32 "
        "{%0,%1,%2,%3}, {%4,%5,%6,%7}, {%8,%9}, {%0,%1,%2,%3};"
        : "+f"(c[0]), "+f"(c[1]), "+f"(c[2]), "+f"(c[3])
        : "r"(a[0]), "r"(a[1]), "r"(a[2]), "r"(a[3]), "r"(b[0]), "r"(b[1]));
}

__device__ __forceinline__ void split_h2(float a, float b, uint32_t& hi, uint32_t& lo) {
    __half ha = __float2half_rn(a), hb = __float2half_rn(b);
    float ra = a - __half2float(ha), rb = b - __half2float(hb);
    __half2 h = __halves2half2(ha, hb);
    __half2 l = __halves2half2(__float2half_rn(ra), __float2half_rn(rb));
    hi = *(uint32_t*)&h;
    lo = *(uint32_t*)&l;
}

// One-time W -> fragment-layout fp16 hi/lo planes (mirrors gate's read mapping).
__global__ void prep_w(const float* __restrict__ w) {
    int idx = blockIdx.x * 256 + threadIdx.x;      // uint4 id, 0..16383
    int lane = idx & 31;
    int r4   = (idx >> 5) & 3;
    int g    = (idx >> 7) & 1;
    int c    = idx >> 8;
    int qid  = lane & 3, grp = lane >> 2;
    uint32_t hi4[4], lo4[4];
#pragma unroll
    for (int i = 0; i < 4; i++) {
        int r  = r4 * 4 + i;
        int q  = r >> 3, nt = (r >> 1) & 3, b = r & 1;
        int n  = g * 32 + nt * 8 + grp;
        int k  = c * 32 + 16 * q + 2 * qid + 8 * b;
        split_h2(w[n * HDIM + k], w[n * HDIM + k + 1], hi4[i], lo4[i]);
    }
    g_whi[idx] = make_uint4(hi4[0], hi4[1], hi4[2], hi4[3]);
    g_wlo[idx] = make_uint4(lo4[0], lo4[1], lo4[2], lo4[3]);
}

__global__ __launch_bounds__(NTHR, 3) void gate_kernel(
    const float* __restrict__ x, const float* __restrict__ w,
    float* __restrict__ out, int T, int S)
{
    extern __shared__ char smraw[];
    __half* smemh = (__half*)smraw;
    float*  lg    = (float*)smraw;        // logits overlay after GEMM
    __shared__ float cnt_s[NEXP];

    const int tid  = threadIdx.x;
    const int wid  = tid >> 5;
    const int lane = tid & 31;
    const int grp  = lane >> 2;
    const int qid  = lane & 3;
    const int t0   = blockIdx.x * BM;
    const int mrow0 = (wid & 1) * 32;     // 2 warps in M (32 rows each)
    const int g     = wid >> 1;           // 2 warps in N (32 cols each)
    const int ncol0 = g * 32;

    if (tid < NEXP) cnt_s[tid] = 0.f;

    float acc[2][4][4];
#pragma unroll
    for (int mt = 0; mt < 2; mt++)
#pragma unroll
        for (int nt = 0; nt < 4; nt++)
#pragma unroll
            for (int k = 0; k < 4; k++) acc[mt][nt][k] = 0.f;

    const float* xbase = x + (size_t)t0 * HDIM;
    const uint4* WH = g_whi + g * 128 + lane;
    const uint4* WL = g_wlo + g * 128 + lane;

    float4 rx[4];
    auto ldg_chunk = [&](int c) {
#pragma unroll
        for (int i = 0; i < 4; i++) {     // 64 rows x 8 segs = 512 float4
            int id = tid + NTHR * i;
            rx[i] = *(const float4*)(xbase + (size_t)(id >> 3) * HDIM + c * KC + (id & 7) * 4);
        }
    };
    auto sts_chunk = [&](int st) {
        __half* stg = smemh + st * STG_HALVES;
#pragma unroll
        for (int i = 0; i < 4; i++) {
            int id = tid + NTHR * i;
            int idx = (id >> 3) * PH + (id & 7) * 4;
            uint32_t h0, l0, h1, l1;
            split_h2(rx[i].x, rx[i].y, h0, l0);
            split_h2(rx[i].z, rx[i].w, h1, l1);
            *(uint2*)(stg + idx)              = make_uint2(h0, h1);
            *(uint2*)(stg + BM * PH + idx)    = make_uint2(l0, l1);
        }
    };

    ldg_chunk(0);

    for (int c = 0; c < NCHUNK; c++) {
        const int st = c & 1;
        sts_chunk(st);
        __syncthreads();
        if (c + 1 < NCHUNK) ldg_chunk(c + 1);

        uint4 H[4], L[4];
#pragma unroll
        for (int r = 0; r < 4; r++) {
            H[r] = WH[c * 256 + r * 32];
            L[r] = WL[c * 256 + r * 32];
        }

        const __half* stg = smemh + st * STG_HALVES;
        const uint32_t* Ah = (const uint32_t*)stg;
        const uint32_t* Al = (const uint32_t*)(stg + BM * PH);

#pragma unroll
        for (int q = 0; q < 2; q++) {
            const int kb = 8 * q + qid;
            uint32_t ah[2][4], al[2][4];
#pragma unroll
            for (int mt = 0; mt < 2; mt++)
#pragma unroll
                for (int j = 0; j < 4; j++) {
                    int off = (mrow0 + 16 * mt + grp + 8 * (j & 1)) * 20 + kb + 4 * (j >> 1);
                    ah[mt][j] = Ah[off];
                    al[mt][j] = Al[off];
                }
            uint32_t bh[4][2], bl[4][2];
            {
                uint4 h0 = H[2 * q], h1 = H[2 * q + 1];
                uint4 l0 = L[2 * q], l1 = L[2 * q + 1];
                bh[0][0] = h0.x; bh[0][1] = h0.y; bh[1][0] = h0.z; bh[1][1] = h0.w;
                bh[2][0] = h1.x; bh[2][1] = h1.y; bh[3][0] = h1.z; bh[3][1] = h1.w;
                bl[0][0] = l0.x; bl[0][1] = l0.y; bl[1][0] = l0.z; bl[1][1] = l0.w;
                bl[2][0] = l1.x; bl[2][1] = l1.y; bl[3][0] = l1.z; bl[3][1] = l1.w;
            }
            // per-(m,n) sequence identical to R10: q0 hh,hl,lh then q1 hh,hl,lh
#pragma unroll
            for (int nt = 0; nt < 4; nt++)
#pragma unroll
                for (int mt = 0; mt < 2; mt++) mma_f16(acc[mt][nt], ah[mt], bh[nt]);
#pragma unroll
            for (int nt = 0; nt < 4; nt++)
#pragma unroll
                for (int mt = 0; mt < 2; mt++) mma_f16(acc[mt][nt], ah[mt], bl[nt]);
#pragma unroll
            for (int nt = 0; nt < 4; nt++)
#pragma unroll
                for (int mt = 0; mt < 2; mt++) mma_f16(acc[mt][nt], al[mt], bh[nt]);
        }
        __syncthreads();
    }

    // ---- logits -> smem ----
#pragma unroll
    for (int mt = 0; mt < 2; mt++)
#pragma unroll
        for (int nt = 0; nt < 4; nt++) {
            int row = mrow0 + 16 * mt + grp;
            int col = ncol0 + nt * 8 + 2 * qid;
            lg[row * LG_PITCH + col]           = acc[mt][nt][0];
            lg[row * LG_PITCH + col + 1]       = acc[mt][nt][1];
            lg[(row + 8) * LG_PITCH + col]     = acc[mt][nt][2];
            lg[(row + 8) * LG_PITCH + col + 1] = acc[mt][nt][3];
        }
    __syncthreads();

    // ---- per-token epilogue (threads 0..63) ----
    if (tid < BM) {
        float sc[NEXP];
        float mx = -1e30f;
#pragma unroll
        for (int e = 0; e < NEXP; e++) { sc[e] = lg[tid * LG_PITCH + e]; mx = fmaxf(mx, sc[e]); }
        float sum = 0.f;
#pragma unroll
        for (int e = 0; e < NEXP; e++) { sc[e] = __expf(sc[e] - mx); sum += sc[e]; }
        float inv = 1.f / sum;
#pragma unroll
        for (int e = 0; e < NEXP; e++) sc[e] *= inv;
#pragma unroll
        for (int e = 0; e < NEXP; e++) lg[tid * LG_PITCH + e] = sc[e];

        float vsel[KTOP + 1]; int isel[KTOP + 1]; float wsum = 0.f;
#pragma unroll
        for (int j = 0; j < KTOP + 1; j++) {
            float bv = -1.f; int bi = 0;
#pragma unroll
            for (int e = 0; e < NEXP; e++) if (sc[e] > bv) { bv = sc[e]; bi = e; }
            vsel[j] = bv; isel[j] = bi;
#pragma unroll
            for (int e = 0; e < NEXP; e++) if (e == bi) sc[e] = -1.f;
            if (j < KTOP) { wsum += bv; atomicAdd(&cnt_s[bi], 1.f); }
        }
        bool flag = false;
#pragma unroll
        for (int j = 0; j < KTOP; j++)
            if (vsel[j] - vsel[j + 1] < vsel[j] * 1e-3f + 2e-6f) flag = true;

        size_t t = (size_t)t0 + tid;
        if (flag) {
            int p = atomicAdd(&g_flag_cnt, 1);
            g_flag_idx[p] = (int)t;
        }
        float rn = 1.f / (wsum + 1e-20f);
#pragma unroll
        for (int j = 0; j < KTOP; j++) {
            out[t * KTOP + j] = (float)isel[j];
            out[(size_t)T * KTOP + t * KTOP + j] = vsel[j] * rn;
        }
    }
    __syncthreads();

    if (tid < NEXP) {
        float pe = 0.f;
#pragma unroll 8
        for (int m = 0; m < BM; m++) pe += lg[m * LG_PITCH + tid];
        g_pi_part[blockIdx.x * NEXP + tid]  = pe;
        g_cnt_part[blockIdx.x * NEXP + tid] = cnt_s[tid];
    }
}

// Exact-fp32 fixup (R9 config: best measured tail): sequential-k fma chain per
// (token, expert) -- arithmetic order matched the reference exactly in R1.
__global__ __launch_bounds__(256) void fixup_kernel(
    const float* __restrict__ x, const float* __restrict__ w,
    float* __restrict__ out, int T)
{
    __shared__ float4 ws4[8 * 66];
    __shared__ float4 xs4[FTOK * 9];
    __shared__ float  lgs[FTOK][72];

    const int tid = threadIdx.x;
    const int e   = tid & 63;
    const int tp  = tid >> 6;
    const int nflag = g_flag_cnt;

    const int wr0 = tid >> 3,        wq = tid & 7;
    const int wr1 = (tid + 256) >> 3;
    const int xt  = tid >> 3,        xq = tid & 7;

    for (int base = blockIdx.x * FTOK; base < nflag; base += FGRID * FTOK) {
        float acc[8];
#pragma unroll
        for (int u = 0; u < 8; u++) acc[u] = 0.f;

        int fi = (base + xt < nflag) ? g_flag_idx[base + xt] : g_flag_idx[base];

        float4 pw0 = *(const float4*)(w + (size_t)wr0 * HDIM + wq * 4);
        float4 pw1 = *(const float4*)(w + (size_t)wr1 * HDIM + wq * 4);
        float4 px  = *(const float4*)(x + (size_t)fi * HDIM + xq * 4);

        for (int c = 0; c < 64; c++) {
            ws4[wq * 66 + wr0] = pw0;
            ws4[wq * 66 + wr1] = pw1;
            xs4[xt * 9 + xq]   = px;
            __syncthreads();

            if (c < 63) {
                pw0 = *(const float4*)(w + (size_t)wr0 * HDIM + (c + 1) * 32 + wq * 4);
                pw1 = *(const float4*)(w + (size_t)wr1 * HDIM + (c + 1) * 32 + wq * 4);
                px  = *(const float4*)(x + (size_t)fi * HDIM + (c + 1) * 32 + xq * 4);
            }
#pragma unroll
            for (int kq = 0; kq < 8; kq++) {
                float4 wv = ws4[kq * 66 + e];
#pragma unroll
                for (int u = 0; u < 8; u++) {
                    float4 xv = xs4[(8 * tp + u) * 9 + kq];
                    acc[u] = fmaf(xv.x, wv.x, acc[u]);
                    acc[u] = fmaf(xv.y, wv.y, acc[u]);
                    acc[u] = fmaf(xv.z, wv.z, acc[u]);
                    acc[u] = fmaf(xv.w, wv.w, acc[u]);
                }
            }
            __syncthreads();
        }

#pragma unroll
        for (int u = 0; u < 8; u++) lgs[8 * tp + u][e] = acc[u];
        __syncthreads();

        if (tid < FTOK && base + tid < nflag) {
            int t = g_flag_idx[base + tid];
            float sc[NEXP];
            float mx = -1e30f;
#pragma unroll
            for (int j = 0; j < NEXP; j++) { sc[j] = lgs[tid][j]; mx = fmaxf(mx, sc[j]); }
            float sum = 0.f;
#pragma unroll
            for (int j = 0; j < NEXP; j++) { sc[j] = __expf(sc[j] - mx); sum += sc[j]; }
            float inv = 1.f / sum;
#pragma unroll
            for (int j = 0; j < NEXP; j++) sc[j] *= inv;

            float wsel[KTOP]; int isel[KTOP]; float wsum = 0.f;
#pragma unroll
            for (int j = 0; j < KTOP; j++) {
                float bv = -1.f; int bi = 0;
#pragma unroll
                for (int e2 = 0; e2 < NEXP; e2++) if (sc[e2] > bv) { bv = sc[e2]; bi = e2; }
                wsel[j] = bv; isel[j] = bi; wsum += bv;
                sc[bi] = -1.f;
            }
            float rn = 1.f / (wsum + 1e-20f);
#pragma unroll
            for (int j = 0; j < KTOP; j++) {
                out[(size_t)t * KTOP + j] = (float)isel[j];
                out[(size_t)T * KTOP + (size_t)t * KTOP + j] = wsel[j] * rn;
            }
        }
        __syncthreads();
    }
}

__global__ void loss_kernel(float* __restrict__ out, int T, int S, int B) {
    __shared__ float red[256];
    int tid = threadIdx.x;
    if (tid == 0) g_flag_cnt = 0;
    int b = tid >> 6, e = tid & 63;
    float ps = 0.f, cs = 0.f;
    int blk0 = b * (NBLK / 4);
    for (int blk = blk0; blk < blk0 + NBLK / 4; blk++) {
        ps += g_pi_part[blk * NEXP + e];
        cs += g_cnt_part[blk * NEXP + e];
    }
    float pi = ps / (float)S;
    float fi = cs * ((float)NEXP / (float)(S * KTOP));
    red[tid] = pi * fi;
    __syncthreads();
    for (int s = 128; s > 0; s >>= 1) {
        if (tid < s) red[tid] += red[tid + s];
        __syncthreads();
    }
    if (tid == 0)
        out[(size_t)2 * T * KTOP] = red[0] * 0.01f / (float)B;
}

extern "C" void kernel_launch(void* const* d_in, const int* in_sizes, int n_in,
                              void* d_out, int out_size)
{
    const float* x = (const float*)d_in[0];
    const float* w = (const float*)d_in[1];
    float* out = (float*)d_out;

    int Hrt = in_sizes[1] / NEXP;    // 2048
    int T   = in_sizes[0] / Hrt;     // 16384
    int B   = 4;
    int S   = T / B;                 // 4096

    size_t smem_bytes = 2 * STG_HALVES * sizeof(__half);   // 20480
    cudaFuncSetAttribute(gate_kernel, cudaFuncAttributeMaxDynamicSharedMemorySize,
                         (int)smem_bytes);

    prep_w<<<64, 256>>>(w);
    gate_kernel<<<T / BM, NTHR, smem_bytes>>>(x, w, out, T, S);
    fixup_kernel<<<FGRID, 256>>>(x, w, out, T);
    loss_kernel<<<1, 256>>>(out, T, S, B);
}